// round 15
// baseline (speedup 1.0000x reference)
#include <cuda_runtime.h>
#include <cuda_fp16.h>
#include <cstdint>

#define S 512
#define YROW 176               // bytes per pixel row in Y (11 x 16B, conflict-free)
#define PCOL 112               // bytes per partials column (96 data + 16 pad)
#define SDXP 20                // pixel stride (floats) for dx staging

// ---- smem byte offsets ----
#define OFF_Y     0                               // 128 * 176 = 22528 B
#define OFF_PART  22528                           // 130 * 112 = 14560 B
#define OFF_B1    (OFF_PART + 14560)              // 37088
#define OFF_B2    (OFF_B1 + 64*4)
#define OFF_B3    (OFF_B2 + 32*4)
#define SMEM_BYTES (OFF_B3 + 16*4)                // 37536 -> 6 CTAs/SM (220KB)

__device__ uint2 gW1f[5*8*32];    // [kc][n][lane] -> {b0,b1} fp16x2, K reordered f*16+ch
__device__ uint2 gW2f[4*4*32];
__device__ uint2 gW3f[2*2*32];

// ---------------- helpers ----------------
static __device__ __forceinline__ uint32_t smem_u32(const void* p) {
    uint32_t a;
    asm("{ .reg .u64 t; cvta.to.shared.u64 t, %1; cvt.u32.u64 %0, t; }" : "=r"(a) : "l"(p));
    return a;
}
static __device__ __forceinline__ uint32_t pkhf(float hi, float lo) {
    uint32_t d; asm("cvt.rn.f16x2.f32 %0, %1, %2;" : "=r"(d) : "f"(hi), "f"(lo)); return d;
}
static __device__ __forceinline__ float swishf(float z) {
    float th;
    asm("tanh.approx.f32 %0, %1;" : "=f"(th) : "f"(0.5f * z));
    return z * fmaf(0.5f, th, 0.5f);
}
static __device__ __forceinline__ void mma_f16(float* c, const uint32_t* a,
                                               uint32_t b0, uint32_t b1) {
    asm("mma.sync.aligned.m16n8k16.row.col.f32.f16.f16.f32 "
        "{%0,%1,%2,%3}, {%4,%5,%6,%7}, {%8,%9}, {%0,%1,%2,%3};"
        : "+f"(c[0]), "+f"(c[1]), "+f"(c[2]), "+f"(c[3])
        : "r"(a[0]), "r"(a[1]), "r"(a[2]), "r"(a[3]), "r"(b0), "r"(b1));
}
static __device__ __forceinline__ void ldsm4(uint32_t* r, uint32_t addr) {
    asm volatile("ldmatrix.sync.aligned.m8n8.x4.shared.b16 {%0,%1,%2,%3}, [%4];"
        : "=r"(r[0]), "=r"(r[1]), "=r"(r[2]), "=r"(r[3]) : "r"(addr));
}
static __device__ __forceinline__ uint4 lds128(uint32_t addr) {
    uint4 v;
    asm volatile("ld.shared.v4.b32 {%0,%1,%2,%3}, [%4];"
        : "=r"(v.x), "=r"(v.y), "=r"(v.z), "=r"(v.w) : "r"(addr));
    return v;
}
static __device__ __forceinline__ void sts128(uint32_t addr, uint32_t a, uint32_t b,
                                              uint32_t c, uint32_t d) {
    asm volatile("st.shared.v4.b32 [%0], {%1,%2,%3,%4};"
        :: "r"(addr), "r"(a), "r"(b), "r"(c), "r"(d) : "memory");
}
static __device__ __forceinline__ void sts64(uint32_t addr, uint32_t a, uint32_t b) {
    asm volatile("st.shared.v2.b32 [%0], {%1,%2};"
        :: "r"(addr), "r"(a), "r"(b) : "memory");
}
static __device__ __forceinline__ uint4 shflu4(uint4 v) {
    uint4 r;
    r.x = __shfl_up_sync(0xffffffffu, v.x, 1);
    r.y = __shfl_up_sync(0xffffffffu, v.y, 1);
    r.z = __shfl_up_sync(0xffffffffu, v.z, 1);
    r.w = __shfl_up_sync(0xffffffffu, v.w, 1);
    return r;
}
static __device__ __forceinline__ uint4 shfld4(uint4 v) {
    uint4 r;
    r.x = __shfl_down_sync(0xffffffffu, v.x, 1);
    r.y = __shfl_down_sync(0xffffffffu, v.y, 1);
    r.z = __shfl_down_sync(0xffffffffu, v.z, 1);
    r.w = __shfl_down_sync(0xffffffffu, v.w, 1);
    return r;
}
static __device__ __forceinline__ __half2 getg(uint4 v, int g) {
    uint32_t u = (g == 0) ? v.x : (g == 1) ? v.y : (g == 2) ? v.z : v.w;
    return *reinterpret_cast<__half2*>(&u);
}
static __device__ __forceinline__ uint32_t h2u(__half2 h) {
    return *reinterpret_cast<uint32_t*>(&h);
}
static __device__ __forceinline__ void swish_pack(const float* acc, float2 bb, uint32_t* h) {
    float s0 = swishf(acc[0] + bb.x);
    float s1 = swishf(acc[1] + bb.y);
    float s2 = swishf(acc[2] + bb.x);
    float s3 = swishf(acc[3] + bb.y);
    h[0] = pkhf(s1, s0);
    h[1] = pkhf(s3, s2);
}

// ---------------- weight prep ----------------
// W1 K reordered: k_new = f*16 + ch  ->  original row = ch*5 + f
static __device__ __forceinline__ int w1row(int k) { return (k & 15) * 5 + (k >> 4); }
static __device__ __forceinline__ uint2 mkfrag1(const float* W1, int col, int r0, int r1) {
    float a0 = W1[w1row(2*r0)*64 + col],   a1 = W1[w1row(2*r0+1)*64 + col];
    float c0 = W1[w1row(2*r1)*64 + col],   c1 = W1[w1row(2*r1+1)*64 + col];
    return make_uint2(pkhf(a1, a0), pkhf(c1, c0));
}
static __device__ __forceinline__ uint2 mkfrag(const float* W, int ncols, int col,
                                               int r0, int r1) {
    float a0 = W[(2*r0)*ncols + col],  a1 = W[(2*r0+1)*ncols + col];
    float c0 = W[(2*r1)*ncols + col],  c1 = W[(2*r1+1)*ncols + col];
    return make_uint2(pkhf(a1, a0), pkhf(c1, c0));
}
__global__ void prep_weights(const float* __restrict__ W1, const float* __restrict__ W2,
                             const float* __restrict__ W3) {
    int i0 = blockIdx.x * blockDim.x + threadIdx.x;
    int nt = gridDim.x * blockDim.x;
    for (int i = i0; i < 5*8*32; i += nt) {
        int lane = i & 31, n = (i >> 5) & 7, kc = i >> 8;
        int g = lane >> 2, t = lane & 3;
        gW1f[i] = mkfrag1(W1, n*8 + g, kc*8 + t, kc*8 + t + 4);
    }
    for (int i = i0; i < 4*4*32; i += nt) {
        int lane = i & 31, n = (i >> 5) & 3, kc = i >> 7;
        int g = lane >> 2, t = lane & 3;
        gW2f[i] = mkfrag(W2, 32, n*8 + g, kc*8 + t, kc*8 + t + 4);
    }
    for (int i = i0; i < 2*2*32; i += nt) {
        int lane = i & 31, n = (i >> 5) & 1, kc = i >> 6;
        int g = lane >> 2, t = lane & 3;
        gW3f[i] = mkfrag(W3, 16, n*8 + g, kc*8 + t, kc*8 + t + 4);
    }
}

// ---------------- main kernel ----------------
__global__ void __launch_bounds__(128, 6) nca_mma(
    const float* __restrict__ xin, const float* __restrict__ noise,
    const float* __restrict__ b1, const float* __restrict__ b2, const float* __restrict__ b3,
    float* __restrict__ out)
{
    extern __shared__ __align__(16) char smem[];
    const uint32_t sYb = smem_u32(smem + OFF_Y);
    const uint32_t sPb = smem_u32(smem + OFF_PART);

    const int tid = threadIdx.x;
    const int lane = tid & 31;
    const int R = (tid >> 5) * 32;
    const int g = lane >> 2;
    const int t = lane & 3;

    const int blk = blockIdx.x;
    const int c0 = (blk & 3) * 128;
    const int y  = (blk >> 2) & (S - 1);
    const int b  = blk >> 11;

    const float4* xin4 = (const float4*)xin;
    {
        float* B1 = (float*)(smem + OFF_B1);
        float* B2 = (float*)(smem + OFF_B2);
        float* B3 = (float*)(smem + OFF_B3);
        if (tid < 64) B1[tid] = b1[tid];
        else if (tid < 96) B2[tid-64] = b2[tid-64];
        else if (tid < 112) B3[tid-96] = b3[tid-96];
    }

    // ---- vertical partials, COALESCED: item i = col*4 + cg ----
    // c = a1, P2 = a0 + 2a1 + a2, d = a2 - a0  (fp32 math -> fp16 pairs)
    const bool tp = y > 0, bt = y < S - 1;
    {
        const size_t rowbase = ((size_t)b * S + y) * S + (c0 - 1);  // col 0 -> gx = c0-1
        #pragma unroll
        for (int it = 0; it < 5; it++) {
            int i = tid + it * 128;
            if (i < 520) {
                int col = i >> 2, cg = i & 3;
                int gx = c0 - 1 + col;
                bool inx = (unsigned)gx < (unsigned)S;
                float4 z = make_float4(0.f, 0.f, 0.f, 0.f);
                float4 r0 = z, r1 = z, r2 = z;
                if (inx) {
                    size_t fi = (rowbase + col) * 4 + cg;   // = base + i : coalesced
                    if (tp) r0 = xin4[fi - (size_t)S * 4];
                            r1 = xin4[fi];
                    if (bt) r2 = xin4[fi + (size_t)S * 4];
                }
                float px = fmaf(2.f, r1.x, r0.x + r2.x);
                float py = fmaf(2.f, r1.y, r0.y + r2.y);
                float pz = fmaf(2.f, r1.z, r0.z + r2.z);
                float pw = fmaf(2.f, r1.w, r0.w + r2.w);
                uint32_t cb = sPb + (uint32_t)col * PCOL + (uint32_t)cg * 8;
                sts64(cb,      pkhf(r1.y, r1.x), pkhf(r1.w, r1.z));
                sts64(cb + 32, pkhf(py, px),     pkhf(pw, pz));
                sts64(cb + 64, pkhf(r2.y - r0.y, r2.x - r0.x),
                               pkhf(r2.w - r0.w, r2.z - r0.z));
            }
        }
    }
    __syncthreads();

    // ---- horizontal combine: center column LDS, neighbors via warp shuffle ----
    const uint32_t myrow = sYb + (uint32_t)tid * YROW;
    {
        const __half2 two    = __float2half2_rn(2.0f);
        const __half2 eighth = __float2half2_rn(0.125f);
        const __half2 quart  = __float2half2_rn(0.25f);
        const __half2 neg4   = __float2half2_rn(-4.0f);
        const __half2 ninth  = __float2half2_rn(1.0f / 9.0f);
        const uint32_t colM = sPb + (uint32_t)(tid + 1) * PCOL;   // this pixel's column
        #pragma unroll
        for (int hb = 0; hb < 2; hb++) {
            uint32_t off = (uint32_t)(hb * 16);
            uint4 cMv = lds128(colM + off);
            uint4 pMv = lds128(colM + 32 + off);
            uint4 dMv = lds128(colM + 64 + off);
            uint4 cLv = shflu4(cMv), pLv = shflu4(pMv), dLv = shflu4(dMv);
            uint4 cRv = shfld4(cMv), pRv = shfld4(pMv), dRv = shfld4(dMv);
            if (lane == 0) {
                uint32_t cl = colM - PCOL;
                cLv = lds128(cl + off);
                pLv = lds128(cl + 32 + off);
                dLv = lds128(cl + 64 + off);
            }
            if (lane == 31) {
                uint32_t cr = colM + PCOL;
                cRv = lds128(cr + off);
                pRv = lds128(cr + 32 + off);
                dRv = lds128(cr + 64 + off);
            }
            uint32_t Yf[5][4];
            #pragma unroll
            for (int gi = 0; gi < 4; gi++) {
                __half2 cL = getg(cLv, gi), cM = getg(cMv, gi), cR = getg(cRv, gi);
                __half2 pL = getg(pLv, gi), pM = getg(pMv, gi), pR = getg(pRv, gi);
                __half2 dL = getg(dLv, gi), dM = getg(dMv, gi), dR = getg(dRv, gi);
                __half2 u   = __hadd2(pL, pR);
                __half2 f0  = cM;
                __half2 f1  = __hmul2(__hsub2(pR, pL), eighth);
                __half2 f2  = __hmul2(__hfma2(dM, two, __hadd2(dL, dR)), eighth);
                __half2 t3  = __hfma2(pM, two, u);
                __half2 f3  = __hfma2(cM, neg4, __hmul2(t3, quart));
                __half2 cs  = __hadd2(__hadd2(cL, cR), cM);
                __half2 f4  = __hmul2(__hsub2(__hadd2(u, pM), cs), ninth);
                Yf[0][gi] = h2u(f0); Yf[1][gi] = h2u(f1); Yf[2][gi] = h2u(f2);
                Yf[3][gi] = h2u(f3); Yf[4][gi] = h2u(f4);
            }
            #pragma unroll
            for (int f = 0; f < 5; f++)
                sts128(myrow + (uint32_t)((2*f + hb) * 16), Yf[f][0], Yf[f][1], Yf[f][2], Yf[f][3]);
        }
    }
    __syncwarp();   // Y rows R..R+31 are warp-local from here on

    const float2* B1v = (const float2*)(smem + OFF_B1);
    const float2* B2v = (const float2*)(smem + OFF_B2);
    const float2* B3v = (const float2*)(smem + OFF_B3);

    const uint32_t lmBase = sYb + (uint32_t)(R + (lane & 15)) * YROW + (uint32_t)(lane >> 4) * 16;

    // ================= layer 1: [128x80] x [80x64], A via ldmatrix =================
    float acc1[8][2][4];
    #pragma unroll
    for (int n = 0; n < 8; n++)
        #pragma unroll
        for (int m = 0; m < 2; m++)
            #pragma unroll
            for (int r = 0; r < 4; r++) acc1[n][m][r] = 0.f;

    #pragma unroll
    for (int kc = 0; kc < 5; kc++) {
        uint2 wf[8];
        #pragma unroll
        for (int n = 0; n < 8; n++) wf[n] = __ldg(&gW1f[(kc*8 + n)*32 + lane]);

        uint32_t ah[2][4];
        ldsm4(ah[0], lmBase + kc*32);
        ldsm4(ah[1], lmBase + 16*YROW + kc*32);
        #pragma unroll
        for (int n = 0; n < 8; n++) {
            #pragma unroll
            for (int m = 0; m < 2; m++)
                mma_f16(acc1[n][m], ah[m], wf[n].x, wf[n].y);
        }
    }

    // ---- H1 = swish(acc1 + b1): register-local repack ----
    uint32_t h1h[8][2][2];
    #pragma unroll
    for (int n = 0; n < 8; n++) {
        float2 bb = B1v[n*4 + t];
        #pragma unroll
        for (int m = 0; m < 2; m++)
            swish_pack(acc1[n][m], bb, h1h[n][m]);
    }

    // ================= layer 2: [128x64] x [64x32], A from registers =================
    float acc2[4][2][4];
    #pragma unroll
    for (int n = 0; n < 4; n++)
        #pragma unroll
        for (int m = 0; m < 2; m++)
            #pragma unroll
            for (int r = 0; r < 4; r++) acc2[n][m][r] = 0.f;

    #pragma unroll
    for (int kc = 0; kc < 4; kc++) {
        uint2 wf[4];
        #pragma unroll
        for (int n = 0; n < 4; n++) wf[n] = __ldg(&gW2f[(kc*4 + n)*32 + lane]);
        #pragma unroll
        for (int m = 0; m < 2; m++) {
            uint32_t ah[4] = { h1h[2*kc][m][0], h1h[2*kc][m][1],
                               h1h[2*kc+1][m][0], h1h[2*kc+1][m][1] };
            #pragma unroll
            for (int n = 0; n < 4; n++)
                mma_f16(acc2[n][m], ah, wf[n].x, wf[n].y);
        }
    }

    // ---- H2 = swish(acc2 + b2) ----
    uint32_t h2h[4][2][2];
    #pragma unroll
    for (int n = 0; n < 4; n++) {
        float2 bb = B2v[n*4 + t];
        #pragma unroll
        for (int m = 0; m < 2; m++)
            swish_pack(acc2[n][m], bb, h2h[n][m]);
    }

    // ================= layer 3: [128x32] x [32x16] =================
    float acc3[2][2][4];
    #pragma unroll
    for (int n = 0; n < 2; n++)
        #pragma unroll
        for (int m = 0; m < 2; m++)
            #pragma unroll
            for (int r = 0; r < 4; r++) acc3[n][m][r] = 0.f;

    #pragma unroll
    for (int kc = 0; kc < 2; kc++) {
        uint2 wf[2];
        #pragma unroll
        for (int n = 0; n < 2; n++) wf[n] = __ldg(&gW3f[(kc*2 + n)*32 + lane]);
        #pragma unroll
        for (int m = 0; m < 2; m++) {
            uint32_t ah[4] = { h2h[2*kc][m][0], h2h[2*kc][m][1],
                               h2h[2*kc+1][m][0], h2h[2*kc+1][m][1] };
            #pragma unroll
            for (int n = 0; n < 2; n++)
                mma_f16(acc3[n][m], ah, wf[n].x, wf[n].y);
        }
    }

    // ---- dx (+bias) staged pixel-major into Y alias (CTA-wide drain first) ----
    __syncthreads();
    float* sDX = (float*)smem;
    #pragma unroll
    for (int n = 0; n < 2; n++) {
        float2 bb = B3v[n*4 + t];
        int ch = n*8 + 2*t;
        #pragma unroll
        for (int m = 0; m < 2; m++) {
            int rA = R + m*16 + g, rB = rA + 8;
            *(float2*)&sDX[rA*SDXP + ch] = make_float2(acc3[n][m][0] + bb.x, acc3[n][m][1] + bb.y);
            *(float2*)&sDX[rB*SDXP + ch] = make_float2(acc3[n][m][2] + bb.x, acc3[n][m][3] + bb.y);
        }
    }
    __syncthreads();

    // ---- coalesced epilogue: out = x + dx * (noise <= 0.5) ----
    {
        const size_t pbase = ((size_t)b * S + y) * S + c0;
        float4* out4 = (float4*)out;
        #pragma unroll
        for (int it2 = 0; it2 < 4; it2++) {
            int i = tid + it2 * 128;
            int px = i >> 2, q = i & 3;
            float4 xv = xin4[(pbase + px) * 4 + q];
            float4 dv = *(const float4*)&sDX[px * SDXP + q * 4];
            float msk = (noise[pbase + px] <= 0.5f) ? 1.f : 0.f;
            out4[(pbase + px) * 4 + q] = make_float4(
                xv.x + dv.x * msk, xv.y + dv.y * msk,
                xv.z + dv.z * msk, xv.w + dv.w * msk);
        }
    }
}

extern "C" void kernel_launch(void* const* d_in, const int* in_sizes, int n_in,
                              void* d_out, int out_size) {
    const float* x     = (const float*)d_in[0];
    const float* noise = (const float*)d_in[1];
    const float* W1    = (const float*)d_in[2];
    const float* b1    = (const float*)d_in[3];
    const float* W2    = (const float*)d_in[4];
    const float* b2    = (const float*)d_in[5];
    const float* W3    = (const float*)d_in[6];
    const float* b3    = (const float*)d_in[7];

    cudaFuncSetAttribute(nca_mma, cudaFuncAttributeMaxDynamicSharedMemorySize, SMEM_BYTES);

    prep_weights<<<10, 128>>>(W1, W2, W3);
    nca_mma<<<8192, 128, SMEM_BYTES>>>(x, noise, b1, b2, b3, (float*)d_out);
}

// round 17
// speedup vs baseline: 1.4583x; 1.4583x over previous
#include <cuda_runtime.h>
#include <cuda_fp16.h>
#include <cstdint>

#define S 512
#define YROW 176               // bytes per pixel row in Y (11 x 16B, conflict-free)
#define PCOL 112               // bytes per partials column (96 data + 16 pad)
#define SDXP 24                // pixel stride (floats) for dx staging (even + conflict-free)

// ---- smem byte offsets ----
#define OFF_Y     0                               // 128 * 176 = 22528 B
#define OFF_PART  22528                           // 130 * 112 = 14560 B
#define OFF_B1    (OFF_PART + 14560)              // 37088
#define OFF_B2    (OFF_B1 + 64*4)
#define OFF_B3    (OFF_B2 + 32*4)
#define SMEM_BYTES (OFF_B3 + 16*4)                // 37536 -> 5 CTAs/SM

__device__ uint2 gW1f[5*8*32];    // [kc][n][lane] -> {b0,b1} fp16x2, K reordered f*16+ch
__device__ uint2 gW2f[4*4*32];
__device__ uint2 gW3f[2*2*32];

// ---------------- helpers ----------------
static __device__ __forceinline__ uint32_t smem_u32(const void* p) {
    uint32_t a;
    asm("{ .reg .u64 t; cvta.to.shared.u64 t, %1; cvt.u32.u64 %0, t; }" : "=r"(a) : "l"(p));
    return a;
}
static __device__ __forceinline__ uint32_t pkhf(float hi, float lo) {
    uint32_t d; asm("cvt.rn.f16x2.f32 %0, %1, %2;" : "=r"(d) : "f"(hi), "f"(lo)); return d;
}
static __device__ __forceinline__ float swishf(float z) {
    float th;
    asm("tanh.approx.f32 %0, %1;" : "=f"(th) : "f"(0.5f * z));
    return z * fmaf(0.5f, th, 0.5f);
}
static __device__ __forceinline__ void mma_f16(float* c, const uint32_t* a,
                                               uint32_t b0, uint32_t b1) {
    asm("mma.sync.aligned.m16n8k16.row.col.f32.f16.f16.f32 "
        "{%0,%1,%2,%3}, {%4,%5,%6,%7}, {%8,%9}, {%0,%1,%2,%3};"
        : "+f"(c[0]), "+f"(c[1]), "+f"(c[2]), "+f"(c[3])
        : "r"(a[0]), "r"(a[1]), "r"(a[2]), "r"(a[3]), "r"(b0), "r"(b1));
}
static __device__ __forceinline__ void ldsm4(uint32_t* r, uint32_t addr) {
    asm volatile("ldmatrix.sync.aligned.m8n8.x4.shared.b16 {%0,%1,%2,%3}, [%4];"
        : "=r"(r[0]), "=r"(r[1]), "=r"(r[2]), "=r"(r[3]) : "r"(addr));
}
static __device__ __forceinline__ uint4 lds128(uint32_t addr) {
    uint4 v;
    asm volatile("ld.shared.v4.b32 {%0,%1,%2,%3}, [%4];"
        : "=r"(v.x), "=r"(v.y), "=r"(v.z), "=r"(v.w) : "r"(addr));
    return v;
}
static __device__ __forceinline__ void sts128(uint32_t addr, uint32_t a, uint32_t b,
                                              uint32_t c, uint32_t d) {
    asm volatile("st.shared.v4.b32 [%0], {%1,%2,%3,%4};"
        :: "r"(addr), "r"(a), "r"(b), "r"(c), "r"(d) : "memory");
}
static __device__ __forceinline__ void sts64(uint32_t addr, uint32_t a, uint32_t b) {
    asm volatile("st.shared.v2.b32 [%0], {%1,%2};"
        :: "r"(addr), "r"(a), "r"(b) : "memory");
}
static __device__ __forceinline__ uint4 shflu4(uint4 v) {
    uint4 r;
    r.x = __shfl_up_sync(0xffffffffu, v.x, 1);
    r.y = __shfl_up_sync(0xffffffffu, v.y, 1);
    r.z = __shfl_up_sync(0xffffffffu, v.z, 1);
    r.w = __shfl_up_sync(0xffffffffu, v.w, 1);
    return r;
}
static __device__ __forceinline__ uint4 shfld4(uint4 v) {
    uint4 r;
    r.x = __shfl_down_sync(0xffffffffu, v.x, 1);
    r.y = __shfl_down_sync(0xffffffffu, v.y, 1);
    r.z = __shfl_down_sync(0xffffffffu, v.z, 1);
    r.w = __shfl_down_sync(0xffffffffu, v.w, 1);
    return r;
}
static __device__ __forceinline__ __half2 getg(uint4 v, int g) {
    uint32_t u = (g == 0) ? v.x : (g == 1) ? v.y : (g == 2) ? v.z : v.w;
    return *reinterpret_cast<__half2*>(&u);
}
static __device__ __forceinline__ uint32_t h2u(__half2 h) {
    return *reinterpret_cast<uint32_t*>(&h);
}
static __device__ __forceinline__ void swish_pack(const float* acc, float2 bb, uint32_t* h) {
    float s0 = swishf(acc[0] + bb.x);
    float s1 = swishf(acc[1] + bb.y);
    float s2 = swishf(acc[2] + bb.x);
    float s3 = swishf(acc[3] + bb.y);
    h[0] = pkhf(s1, s0);
    h[1] = pkhf(s3, s2);
}

// ---------------- weight prep ----------------
// W1 K reordered: k_new = f*16 + ch  ->  original row = ch*5 + f
static __device__ __forceinline__ int w1row(int k) { return (k & 15) * 5 + (k >> 4); }
static __device__ __forceinline__ uint2 mkfrag1(const float* W1, int col, int r0, int r1) {
    float a0 = W1[w1row(2*r0)*64 + col],   a1 = W1[w1row(2*r0+1)*64 + col];
    float c0 = W1[w1row(2*r1)*64 + col],   c1 = W1[w1row(2*r1+1)*64 + col];
    return make_uint2(pkhf(a1, a0), pkhf(c1, c0));
}
static __device__ __forceinline__ uint2 mkfrag(const float* W, int ncols, int col,
                                               int r0, int r1) {
    float a0 = W[(2*r0)*ncols + col],  a1 = W[(2*r0+1)*ncols + col];
    float c0 = W[(2*r1)*ncols + col],  c1 = W[(2*r1+1)*ncols + col];
    return make_uint2(pkhf(a1, a0), pkhf(c1, c0));
}
__global__ void prep_weights(const float* __restrict__ W1, const float* __restrict__ W2,
                             const float* __restrict__ W3) {
    int i0 = blockIdx.x * blockDim.x + threadIdx.x;
    int nt = gridDim.x * blockDim.x;
    for (int i = i0; i < 5*8*32; i += nt) {
        int lane = i & 31, n = (i >> 5) & 7, kc = i >> 8;
        int g = lane >> 2, t = lane & 3;
        gW1f[i] = mkfrag1(W1, n*8 + g, kc*8 + t, kc*8 + t + 4);
    }
    for (int i = i0; i < 4*4*32; i += nt) {
        int lane = i & 31, n = (i >> 5) & 3, kc = i >> 7;
        int g = lane >> 2, t = lane & 3;
        gW2f[i] = mkfrag(W2, 32, n*8 + g, kc*8 + t, kc*8 + t + 4);
    }
    for (int i = i0; i < 2*2*32; i += nt) {
        int lane = i & 31, n = (i >> 5) & 1, kc = i >> 6;
        int g = lane >> 2, t = lane & 3;
        gW3f[i] = mkfrag(W3, 16, n*8 + g, kc*8 + t, kc*8 + t + 4);
    }
}

// ---------------- main kernel ----------------
__global__ void __launch_bounds__(128, 5) nca_mma(
    const float* __restrict__ xin, const float* __restrict__ noise,
    const float* __restrict__ b1, const float* __restrict__ b2, const float* __restrict__ b3,
    float* __restrict__ out)
{
    extern __shared__ __align__(16) char smem[];
    const uint32_t sYb = smem_u32(smem + OFF_Y);
    const uint32_t sPb = smem_u32(smem + OFF_PART);

    const int tid = threadIdx.x;
    const int lane = tid & 31;
    const int R = (tid >> 5) * 32;
    const int g = lane >> 2;
    const int t = lane & 3;

    const int blk = blockIdx.x;
    const int c0 = (blk & 3) * 128;
    const int y  = (blk >> 2) & (S - 1);
    const int b  = blk >> 11;

    const float4* xin4 = (const float4*)xin;
    {
        float* B1 = (float*)(smem + OFF_B1);
        float* B2 = (float*)(smem + OFF_B2);
        float* B3 = (float*)(smem + OFF_B3);
        if (tid < 64) B1[tid] = b1[tid];
        else if (tid < 96) B2[tid-64] = b2[tid-64];
        else if (tid < 112) B3[tid-96] = b3[tid-96];
    }

    // ---- vertical partials, COALESCED: item i = col*4 + cg ----
    // c = a1, P2 = a0 + 2a1 + a2, d = a2 - a0  (fp32 math -> fp16 pairs)
    const bool tp = y > 0, bt = y < S - 1;
    {
        const size_t rowbase = ((size_t)b * S + y) * S + (c0 - 1);  // col 0 -> gx = c0-1
        #pragma unroll
        for (int it = 0; it < 5; it++) {
            int i = tid + it * 128;
            if (i < 520) {
                int col = i >> 2, cg = i & 3;
                int gx = c0 - 1 + col;
                bool inx = (unsigned)gx < (unsigned)S;
                float4 z = make_float4(0.f, 0.f, 0.f, 0.f);
                float4 r0 = z, r1 = z, r2 = z;
                if (inx) {
                    size_t fi = (rowbase + col) * 4 + cg;   // = base + i : coalesced
                    if (tp) r0 = xin4[fi - (size_t)S * 4];
                            r1 = xin4[fi];
                    if (bt) r2 = xin4[fi + (size_t)S * 4];
                }
                float px = fmaf(2.f, r1.x, r0.x + r2.x);
                float py = fmaf(2.f, r1.y, r0.y + r2.y);
                float pz = fmaf(2.f, r1.z, r0.z + r2.z);
                float pw = fmaf(2.f, r1.w, r0.w + r2.w);
                uint32_t cb = sPb + (uint32_t)col * PCOL + (uint32_t)cg * 8;
                sts64(cb,      pkhf(r1.y, r1.x), pkhf(r1.w, r1.z));
                sts64(cb + 32, pkhf(py, px),     pkhf(pw, pz));
                sts64(cb + 64, pkhf(r2.y - r0.y, r2.x - r0.x),
                               pkhf(r2.w - r0.w, r2.z - r0.z));
            }
        }
    }
    __syncthreads();

    // ---- horizontal combine: center column LDS, neighbors via warp shuffle ----
    const uint32_t myrow = sYb + (uint32_t)tid * YROW;
    {
        const __half2 two    = __float2half2_rn(2.0f);
        const __half2 eighth = __float2half2_rn(0.125f);
        const __half2 quart  = __float2half2_rn(0.25f);
        const __half2 neg4   = __float2half2_rn(-4.0f);
        const __half2 ninth  = __float2half2_rn(1.0f / 9.0f);
        const uint32_t colM = sPb + (uint32_t)(tid + 1) * PCOL;   // this pixel's column
        #pragma unroll
        for (int hb = 0; hb < 2; hb++) {
            uint32_t off = (uint32_t)(hb * 16);
            uint4 cMv = lds128(colM + off);
            uint4 pMv = lds128(colM + 32 + off);
            uint4 dMv = lds128(colM + 64 + off);
            uint4 cLv = shflu4(cMv), pLv = shflu4(pMv), dLv = shflu4(dMv);
            uint4 cRv = shfld4(cMv), pRv = shfld4(pMv), dRv = shfld4(dMv);
            if (lane == 0) {
                uint32_t cl = colM - PCOL;
                cLv = lds128(cl + off);
                pLv = lds128(cl + 32 + off);
                dLv = lds128(cl + 64 + off);
            }
            if (lane == 31) {
                uint32_t cr = colM + PCOL;
                cRv = lds128(cr + off);
                pRv = lds128(cr + 32 + off);
                dRv = lds128(cr + 64 + off);
            }
            uint32_t Yf[5][4];
            #pragma unroll
            for (int gi = 0; gi < 4; gi++) {
                __half2 cL = getg(cLv, gi), cM = getg(cMv, gi), cR = getg(cRv, gi);
                __half2 pL = getg(pLv, gi), pM = getg(pMv, gi), pR = getg(pRv, gi);
                __half2 dL = getg(dLv, gi), dM = getg(dMv, gi), dR = getg(dRv, gi);
                __half2 u   = __hadd2(pL, pR);
                __half2 f0  = cM;
                __half2 f1  = __hmul2(__hsub2(pR, pL), eighth);
                __half2 f2  = __hmul2(__hfma2(dM, two, __hadd2(dL, dR)), eighth);
                __half2 t3  = __hfma2(pM, two, u);
                __half2 f3  = __hfma2(cM, neg4, __hmul2(t3, quart));
                __half2 cs  = __hadd2(__hadd2(cL, cR), cM);
                __half2 f4  = __hmul2(__hsub2(__hadd2(u, pM), cs), ninth);
                Yf[0][gi] = h2u(f0); Yf[1][gi] = h2u(f1); Yf[2][gi] = h2u(f2);
                Yf[3][gi] = h2u(f3); Yf[4][gi] = h2u(f4);
            }
            #pragma unroll
            for (int f = 0; f < 5; f++)
                sts128(myrow + (uint32_t)((2*f + hb) * 16), Yf[f][0], Yf[f][1], Yf[f][2], Yf[f][3]);
        }
    }
    __syncwarp();   // Y rows R..R+31 are warp-local from here on

    const float2* B1v = (const float2*)(smem + OFF_B1);
    const float2* B2v = (const float2*)(smem + OFF_B2);
    const float2* B3v = (const float2*)(smem + OFF_B3);

    const uint32_t lmBase = sYb + (uint32_t)(R + (lane & 15)) * YROW + (uint32_t)(lane >> 4) * 16;

    // ================= layer 1: [128x80] x [80x64], A via ldmatrix =================
    float acc1[8][2][4];
    #pragma unroll
    for (int n = 0; n < 8; n++)
        #pragma unroll
        for (int m = 0; m < 2; m++)
            #pragma unroll
            for (int r = 0; r < 4; r++) acc1[n][m][r] = 0.f;

    #pragma unroll
    for (int kc = 0; kc < 5; kc++) {
        uint2 wf[8];
        #pragma unroll
        for (int n = 0; n < 8; n++) wf[n] = __ldg(&gW1f[(kc*8 + n)*32 + lane]);

        uint32_t ah[2][4];
        ldsm4(ah[0], lmBase + kc*32);
        ldsm4(ah[1], lmBase + 16*YROW + kc*32);
        #pragma unroll
        for (int n = 0; n < 8; n++) {
            #pragma unroll
            for (int m = 0; m < 2; m++)
                mma_f16(acc1[n][m], ah[m], wf[n].x, wf[n].y);
        }
    }

    // ---- H1 = swish(acc1 + b1): register-local repack ----
    uint32_t h1h[8][2][2];
    #pragma unroll
    for (int n = 0; n < 8; n++) {
        float2 bb = B1v[n*4 + t];
        #pragma unroll
        for (int m = 0; m < 2; m++)
            swish_pack(acc1[n][m], bb, h1h[n][m]);
    }

    // ================= layer 2: [128x64] x [64x32], A from registers =================
    float acc2[4][2][4];
    #pragma unroll
    for (int n = 0; n < 4; n++)
        #pragma unroll
        for (int m = 0; m < 2; m++)
            #pragma unroll
            for (int r = 0; r < 4; r++) acc2[n][m][r] = 0.f;

    #pragma unroll
    for (int kc = 0; kc < 4; kc++) {
        uint2 wf[4];
        #pragma unroll
        for (int n = 0; n < 4; n++) wf[n] = __ldg(&gW2f[(kc*4 + n)*32 + lane]);
        #pragma unroll
        for (int m = 0; m < 2; m++) {
            uint32_t ah[4] = { h1h[2*kc][m][0], h1h[2*kc][m][1],
                               h1h[2*kc+1][m][0], h1h[2*kc+1][m][1] };
            #pragma unroll
            for (int n = 0; n < 4; n++)
                mma_f16(acc2[n][m], ah, wf[n].x, wf[n].y);
        }
    }

    // ---- H2 = swish(acc2 + b2) ----
    uint32_t h2h[4][2][2];
    #pragma unroll
    for (int n = 0; n < 4; n++) {
        float2 bb = B2v[n*4 + t];
        #pragma unroll
        for (int m = 0; m < 2; m++)
            swish_pack(acc2[n][m], bb, h2h[n][m]);
    }

    // ================= layer 3: [128x32] x [32x16] =================
    float acc3[2][2][4];
    #pragma unroll
    for (int n = 0; n < 2; n++)
        #pragma unroll
        for (int m = 0; m < 2; m++)
            #pragma unroll
            for (int r = 0; r < 4; r++) acc3[n][m][r] = 0.f;

    #pragma unroll
    for (int kc = 0; kc < 2; kc++) {
        uint2 wf[2];
        #pragma unroll
        for (int n = 0; n < 2; n++) wf[n] = __ldg(&gW3f[(kc*2 + n)*32 + lane]);
        #pragma unroll
        for (int m = 0; m < 2; m++) {
            uint32_t ah[4] = { h2h[2*kc][m][0], h2h[2*kc][m][1],
                               h2h[2*kc+1][m][0], h2h[2*kc+1][m][1] };
            #pragma unroll
            for (int n = 0; n < 2; n++)
                mma_f16(acc3[n][m], ah, wf[n].x, wf[n].y);
        }
    }

    // ---- dx (+bias) staged pixel-major into Y alias (CTA-wide drain first) ----
    __syncthreads();
    float* sDX = (float*)smem;
    #pragma unroll
    for (int n = 0; n < 2; n++) {
        float2 bb = B3v[n*4 + t];
        int ch = n*8 + 2*t;
        #pragma unroll
        for (int m = 0; m < 2; m++) {
            int rA = R + m*16 + g, rB = rA + 8;
            *(float2*)&sDX[rA*SDXP + ch] = make_float2(acc3[n][m][0] + bb.x, acc3[n][m][1] + bb.y);
            *(float2*)&sDX[rB*SDXP + ch] = make_float2(acc3[n][m][2] + bb.x, acc3[n][m][3] + bb.y);
        }
    }
    __syncthreads();

    // ---- coalesced epilogue: out = x + dx * (noise <= 0.5) ----
    {
        const size_t pbase = ((size_t)b * S + y) * S + c0;
        float4* out4 = (float4*)out;
        #pragma unroll
        for (int it2 = 0; it2 < 4; it2++) {
            int i = tid + it2 * 128;
            int px = i >> 2, q = i & 3;
            float4 xv = xin4[(pbase + px) * 4 + q];
            float4 dv = *(const float4*)&sDX[px * SDXP + q * 4];
            float msk = (noise[pbase + px] <= 0.5f) ? 1.f : 0.f;
            out4[(pbase + px) * 4 + q] = make_float4(
                xv.x + dv.x * msk, xv.y + dv.y * msk,
                xv.z + dv.z * msk, xv.w + dv.w * msk);
        }
    }
}

extern "C" void kernel_launch(void* const* d_in, const int* in_sizes, int n_in,
                              void* d_out, int out_size) {
    const float* x     = (const float*)d_in[0];
    const float* noise = (const float*)d_in[1];
    const float* W1    = (const float*)d_in[2];
    const float* b1    = (const float*)d_in[3];
    const float* W2    = (const float*)d_in[4];
    const float* b2    = (const float*)d_in[5];
    const float* W3    = (const float*)d_in[6];
    const float* b3    = (const float*)d_in[7];

    cudaFuncSetAttribute(nca_mma, cudaFuncAttributeMaxDynamicSharedMemorySize, SMEM_BYTES);

    prep_weights<<<10, 128>>>(W1, W2, W3);
    nca_mma<<<8192, 128, SMEM_BYTES>>>(x, noise, b1, b2, b3, (float*)d_out);
}